// round 5
// baseline (speedup 1.0000x reference)
#include <cuda_runtime.h>

#define NH 256
#define NW 256
#define GH2 512
#define GW2 512
#define NA 5
#define NC 12
#define FREQ (GH2*GW2)   // 262144

#define SZ_X   (NA*NH*NW)      // 327680
#define SZ_MPS (NC*NH*NW)      // 786432
#define SZ_K   (NA*NA*FREQ)    // 6553600

// Scratch: Fx_full (also Y_full, contraction in-place) and Fx_mid (also Y_mid).
__device__ float2 g_full[NC*NA*GH2*GW2];   // 125.8 MB
__device__ float2 g_mid [NC*NA*NH*GW2];    // 62.9 MB

__device__ __forceinline__ float2 cmul(float2 a, float2 b) {
    return make_float2(a.x*b.x - a.y*b.y, a.x*b.y + a.y*b.x);
}

__device__ __forceinline__ void init_tw(float2* tw, int t) {
    float ang = -6.283185307179586f * (float)t * (1.0f/512.0f);
    float sv, cv;
    sincosf(ang, &sv, &cv);
    tw[t] = make_float2(cv, sv);
}

// 512-point Stockham radix-2 DIF, ping-pong b0->b1 (9 passes -> lands in b1).
// Verified by hand against the DFT for N=4 and N=8 (natural order, e^{-} fwd).
template<bool INV, int NF>
__device__ __forceinline__ void fft512(float2 (*b0)[512], float2 (*b1)[512],
                                       const float2* tw, int t) {
    float2 (*s)[512] = b0;
    float2 (*d)[512] = b1;
    #pragma unroll
    for (int k = 0; k < 9; k++) {
        __syncthreads();
        int str = 1 << k;
        int m   = 256 >> k;
        int q   = t & (str - 1);
        int p   = t >> k;
        float2 w = tw[p << k];
        if (INV) w.y = -w.y;
        #pragma unroll
        for (int f = 0; f < NF; f++) {
            float2 a = s[f][q + str*p];
            float2 b = s[f][q + str*(p + m)];
            float2 apb = make_float2(a.x + b.x, a.y + b.y);
            float2 amb = make_float2(a.x - b.x, a.y - b.y);
            d[f][q + str*2*p]       = apb;
            d[f][q + str*(2*p + 1)] = cmul(amb, w);
        }
        float2 (*tmp)[512] = s; s = d; d = tmp;
    }
    __syncthreads();
}

__global__ void zero_out(float* __restrict__ o, int n) {
    int i = blockIdx.x*256 + threadIdx.x;
    if (i < n) o[i] = 0.f;
}

// -------- P1: per (c,b,row r): row-FFT of padded x[b]*mps[c] ----------------
__global__ void __launch_bounds__(256)
p1_rowfft(const float* __restrict__ xr, const float* __restrict__ xi,
          const float* __restrict__ mr, const float* __restrict__ mi) {
    __shared__ float2 tw[256];
    __shared__ float2 b0[1][512], b1[1][512];
    int t = threadIdx.x;
    int r = blockIdx.x, b = blockIdx.y, c = blockIdx.z;
    init_tw(tw, t);
    b0[0][t]       = make_float2(0.f, 0.f);
    b0[0][t + 256] = make_float2(0.f, 0.f);
    __syncthreads();
    int xo = (b*NH + r)*NW + t;
    int mo = (c*NH + r)*NW + t;
    float2 xv = make_float2(xr[xo], xi[xo]);
    float2 mv = make_float2(mr[mo], mi[mo]);
    b0[0][t + 128] = cmul(xv, mv);           // centered pad: cols 128..383
    fft512<false, 1>(b0, b1, tw, t);
    float2* dst = g_mid + (size_t)((c*NA + b)*NH + r)*GW2;
    dst[t]       = b1[0][t];
    dst[t + 256] = b1[0][t + 256];
}

// -------- P2: per (c,b,4 cols): column-FFT with zero-padded rows ------------
__global__ void __launch_bounds__(256)
p2_colfft() {
    __shared__ float2 tw[256];
    __shared__ float2 b0[4][512], b1[4][512];
    int t = threadIdx.x;
    int j0 = blockIdx.x*4, b = blockIdx.y, c = blockIdx.z;
    init_tw(tw, t);
    #pragma unroll
    for (int i = 0; i < 8; i++) {
        int idx = t + 256*i;
        b0[idx & 3][idx >> 2] = make_float2(0.f, 0.f);
    }
    __syncthreads();
    const float2* src = g_mid + (size_t)((c*NA + b)*NH)*GW2;
    #pragma unroll
    for (int i = 0; i < 4; i++) {
        int idx = t + 256*i;
        int r = idx >> 2, f = idx & 3;
        b0[f][r + 128] = src[(size_t)r*GW2 + j0 + f];
    }
    fft512<false, 4>(b0, b1, tw, t);
    float2* dst = g_full + (size_t)(c*NA + b)*FREQ;
    #pragma unroll
    for (int i = 0; i < 8; i++) {
        int idx = t + 256*i;
        int h = idx >> 2, f = idx & 3;
        dst[(size_t)h*GW2 + j0 + f] = b1[f][h];
    }
}

// -------- P3: per-frequency [A,A] contraction, in place, K read once --------
__global__ void __launch_bounds__(256)
p3_contract(const float* __restrict__ kr, const float* __restrict__ ki) {
    int idx = blockIdx.x*256 + threadIdx.x;
    const float SCALE = 1.0f / 65536.0f;     // OS^2 / (512*512) ortho norms
    float2 K[NA*NA];
    #pragma unroll
    for (int q = 0; q < NA*NA; q++) {
        size_t o = (size_t)q*FREQ + idx;
        K[q] = make_float2(kr[o]*SCALE, ki[o]*SCALE);
    }
    for (int c = 0; c < NC; c++) {
        float2 fx[NA];
        #pragma unroll
        for (int b = 0; b < NA; b++)
            fx[b] = g_full[(size_t)(c*NA + b)*FREQ + idx];
        #pragma unroll
        for (int a = 0; a < NA; a++) {
            float2 acc = make_float2(0.f, 0.f);
            #pragma unroll
            for (int b = 0; b < NA; b++) {
                float2 kv = K[a*NA + b];
                float2 f  = fx[b];
                acc.x += f.x*kv.x - f.y*kv.y;
                acc.y += f.x*kv.y + f.y*kv.x;
            }
            g_full[(size_t)(c*NA + a)*FREQ + idx] = acc;
        }
    }
}

// -------- P4: per (c,a,4 cols): column-IFFT, keep only rows 128..383 --------
__global__ void __launch_bounds__(256)
p4_colifft() {
    __shared__ float2 tw[256];
    __shared__ float2 b0[4][512], b1[4][512];
    int t = threadIdx.x;
    int j0 = blockIdx.x*4, a = blockIdx.y, c = blockIdx.z;
    init_tw(tw, t);
    const float2* src = g_full + (size_t)(c*NA + a)*FREQ;
    #pragma unroll
    for (int i = 0; i < 8; i++) {
        int idx = t + 256*i;
        int h = idx >> 2, f = idx & 3;
        b0[f][h] = src[(size_t)h*GW2 + j0 + f];
    }
    fft512<true, 4>(b0, b1, tw, t);
    float2* dst = g_mid + (size_t)((c*NA + a)*NH)*GW2;
    #pragma unroll
    for (int i = 0; i < 4; i++) {
        int idx = t + 256*i;
        int r = idx >> 2, f = idx & 3;
        dst[(size_t)r*GW2 + j0 + f] = b1[f][r + 128];
    }
}

// -------- P5: per (a,row r): 12x row-IFFT, crop, conj(mps), sum_c -----------
// PLANAR output: out[0 .. SZ_X) = real plane, out[SZ_X .. 2*SZ_X) = imag plane.
// Writes clamped to out_cap floats: cannot overflow d_out under any layout.
__global__ void __launch_bounds__(256)
p5_combine(const float* __restrict__ mr, const float* __restrict__ mi,
           float* __restrict__ out, int out_cap) {
    __shared__ float2 tw[256];
    __shared__ float2 b0[1][512], b1[1][512];
    int t = threadIdx.x;
    int r = blockIdx.x, a = blockIdx.y;
    init_tw(tw, t);
    float2 acc = make_float2(0.f, 0.f);
    for (int c = 0; c < NC; c++) {
        const float2* src = g_mid + (size_t)((c*NA + a)*NH + r)*GW2;
        b0[0][t]       = src[t];
        b0[0][t + 256] = src[t + 256];
        fft512<true, 1>(b0, b1, tw, t);
        float2 v = b1[0][t + 128];           // crop: cols 128..383
        int mo = (c*NH + r)*NW + t;
        float2 m = make_float2(mr[mo], -mi[mo]);
        float2 p = cmul(v, m);
        acc.x += p.x;
        acc.y += p.y;
    }
    int i = (a*NH + r)*NW + t;               // complex element index
    if (i        < out_cap) out[i]        = acc.x;   // real plane
    if (i + SZ_X < out_cap) out[i + SZ_X] = acc.y;   // imag plane
}

extern "C" void kernel_launch(void* const* d_in, const int* in_sizes, int n_in,
                              void* d_out, int out_size) {
    // ---- strict binding: accept ONLY a verified size fingerprint ----
    const float *ptr_by_sz[3][2] = {{0,0},{0,0},{0,0}}; // [x|mps|k][first|second]
    int idx_by_sz[3][2] = {{-1,-1},{-1,-1},{-1,-1}};
    bool ok = (n_in == 6);
    if (ok) {
        for (int i = 0; i < 6; i++) {
            long long s = in_sizes[i];
            int which = -1;
            if (s == SZ_X   || s == (long long)SZ_X*4)   which = 0;
            else if (s == SZ_MPS || s == (long long)SZ_MPS*4) which = 1;
            else if (s == SZ_K   || s == (long long)SZ_K*4)   which = 2;
            if (which < 0) { ok = false; break; }
            if      (idx_by_sz[which][0] < 0) { idx_by_sz[which][0] = i; ptr_by_sz[which][0] = (const float*)d_in[i]; }
            else if (idx_by_sz[which][1] < 0) { idx_by_sz[which][1] = i; ptr_by_sz[which][1] = (const float*)d_in[i]; }
            else { ok = false; break; }
        }
        if (ok)
            for (int w = 0; w < 3; w++)
                if (idx_by_sz[w][1] < 0) ok = false;
    }

    if (!ok) {
        int n = out_size > 0 ? out_size : 1;
        zero_out<<<(n + 255)/256, 256>>>((float*)d_out, n);
        return;
    }

    // real/imag convention: dict order (x before kernels) => real first.
    bool real_first = (idx_by_sz[0][0] < idx_by_sz[2][0]);
    const float* xr = ptr_by_sz[0][real_first ? 0 : 1];
    const float* xi = ptr_by_sz[0][real_first ? 1 : 0];
    const float* mr = ptr_by_sz[1][real_first ? 0 : 1];
    const float* mi = ptr_by_sz[1][real_first ? 1 : 0];
    const float* kr = ptr_by_sz[2][real_first ? 0 : 1];
    const float* ki = ptr_by_sz[2][real_first ? 1 : 0];

    p1_rowfft <<<dim3(NH, NA, NC), 256>>>(xr, xi, mr, mi);
    p2_colfft <<<dim3(GW2/4, NA, NC), 256>>>();
    p3_contract<<<FREQ/256, 256>>>(kr, ki);
    p4_colifft<<<dim3(GW2/4, NA, NC), 256>>>();
    p5_combine<<<dim3(NH, NA), 256>>>(mr, mi, (float*)d_out, out_size);
}

// round 6
// speedup vs baseline: 1.7234x; 1.7234x over previous
#include <cuda_runtime.h>

#define NH 256
#define NW 256
#define GH2 512
#define GW2 512
#define NA 5
#define NC 12
#define FREQ (GH2*GW2)   // 262144

#define SZ_X   (NA*NH*NW)      // 327680
#define SZ_MPS (NC*NH*NW)      // 786432
#define SZ_K   (NA*NA*FREQ)    // 6553600

// Skewed smem index: conflict-free for the radix-8 pass patterns (verified by
// bank enumeration for pass-0/2 reads+writes; pass-1 writes ~1.2x).
#define IDX(i) ((i) + ((i) >> 5) + 8*((i) >> 6))
#define SMEM_N 584             // IDX(511) = 582

__device__ float2 g_full[NC*NA*GH2*GW2];   // 125.8 MB
__device__ float2 g_mid [NC*NA*NH*GW2];    // 62.9 MB

__device__ __forceinline__ float2 cadd(float2 a, float2 b) { return make_float2(a.x+b.x, a.y+b.y); }
__device__ __forceinline__ float2 csub(float2 a, float2 b) { return make_float2(a.x-b.x, a.y-b.y); }
__device__ __forceinline__ float2 cmul(float2 a, float2 b) {
    return make_float2(a.x*b.x - a.y*b.y, a.x*b.y + a.y*b.x);
}

// Build tw[j] = exp(-2*pi*i*j/512), j in [0,512). 256 threads, 2 entries each.
__device__ __forceinline__ void build_tw(float2* tw, int t) {
    #pragma unroll
    for (int u = 0; u < 2; u++) {
        int j = t + 256*u;
        float sv, cv;
        sincosf(-6.283185307179586f * (float)j * (1.0f/512.0f), &sv, &cv);
        tw[j] = make_float2(cv, sv);
    }
}

// In-register DFT-8 (DIF). Outputs in natural order x[r].
template<bool INV>
__device__ __forceinline__ void dft8(float2* x) {
    const float H = 0.70710678118654752f;
    float2 t0 = cadd(x[0], x[4]), t4 = csub(x[0], x[4]);
    float2 t1 = cadd(x[1], x[5]), t5 = csub(x[1], x[5]);
    float2 t2 = cadd(x[2], x[6]), t6 = csub(x[2], x[6]);
    float2 t3 = cadd(x[3], x[7]), t7 = csub(x[3], x[7]);
    // t5 *= w8^1, t6 *= w8^2, t7 *= w8^3  (conjugated if INV)
    if (!INV) {
        t5 = make_float2(H*(t5.x + t5.y), H*(t5.y - t5.x));
        t6 = make_float2(t6.y, -t6.x);
        t7 = make_float2(H*(t7.y - t7.x), -H*(t7.x + t7.y));
    } else {
        t5 = make_float2(H*(t5.x - t5.y), H*(t5.x + t5.y));
        t6 = make_float2(-t6.y, t6.x);
        t7 = make_float2(-H*(t7.x + t7.y), H*(t7.x - t7.y));
    }
    float2 u0 = cadd(t0, t2), u2 = csub(t0, t2);
    float2 u1 = cadd(t1, t3), u3 = csub(t1, t3);
    u3 = INV ? make_float2(-u3.y, u3.x) : make_float2(u3.y, -u3.x);
    float2 v0 = cadd(t4, t6), v2 = csub(t4, t6);
    float2 v1 = cadd(t5, t7), v3 = csub(t5, t7);
    v3 = INV ? make_float2(-v3.y, v3.x) : make_float2(v3.y, -v3.x);
    x[0] = cadd(u0, u1); x[4] = csub(u0, u1);
    x[2] = cadd(u2, u3); x[6] = csub(u2, u3);
    x[1] = cadd(v0, v1); x[5] = csub(v0, v1);
    x[3] = cadd(v2, v3); x[7] = csub(v2, v3);
}

// 512-pt FFT, radix-8 Stockham, 3 passes, 64 threads (tl in [0,64)), data in
// skewed smem arrays re/im. Natural order in, natural order out (unnormalized).
template<bool INV>
__device__ __forceinline__ void fft512_r8(float* re, float* im,
                                          const float2* tw, int tl) {
    #pragma unroll
    for (int k = 0; k < 3; k++) {
        const int sh = 3*k;            // s = 1<<sh : 1, 8, 64
        const int s  = 1 << sh;
        int q = tl & (s - 1);
        int p = tl >> sh;              // [0, 64/s); pass 2: p in [0,1)? no: tl>>6=0
        float2 x[8];
        #pragma unroll
        for (int j = 0; j < 8; j++) {  // read at q + s*(p + m*j) = tl + 64*j
            int i = tl + 64*j;
            x[j] = make_float2(re[IDX(i)], im[IDX(i)]);
        }
        __syncthreads();
        dft8<INV>(x);
        int ob = q + ((8*p) << sh);
        #pragma unroll
        for (int r = 0; r < 8; r++) {
            float2 v = x[r];
            if (r > 0 && k < 2) {
                float2 w = tw[(p*r) << sh];
                float wy = INV ? -w.y : w.y;
                v = make_float2(x[r].x*w.x - x[r].y*wy,
                                x[r].x*wy + x[r].y*w.x);
            }
            int o = ob + (r << sh);
            re[IDX(o)] = v.x; im[IDX(o)] = v.y;
        }
        __syncthreads();
    }
}

__global__ void zero_out(float* __restrict__ o, int n) {
    int i = blockIdx.x*256 + threadIdx.x;
    if (i < n) o[i] = 0.f;
}

// -------- P1: 4 rows/block: row-FFT of padded x[b]*mps[c] -------------------
__global__ void __launch_bounds__(256)
p1_rowfft(const float* __restrict__ xr, const float* __restrict__ xi,
          const float* __restrict__ mr, const float* __restrict__ mi) {
    __shared__ float sre[4][SMEM_N], sim[4][SMEM_N];
    __shared__ float2 tw[512];
    int t = threadIdx.x;
    build_tw(tw, t);
    int f = t >> 6, tl = t & 63;
    int row = blockIdx.x*4 + f;
    int b = blockIdx.y, c = blockIdx.z;
    #pragma unroll
    for (int j = 0; j < 8; j++) {
        int i = tl + 64*j;
        float2 v = make_float2(0.f, 0.f);
        if (j >= 2 && j < 6) {
            int col = i - 128;
            int xo = (b*NH + row)*NW + col;
            int mo = (c*NH + row)*NW + col;
            v = cmul(make_float2(xr[xo], xi[xo]), make_float2(mr[mo], mi[mo]));
        }
        sre[f][IDX(i)] = v.x; sim[f][IDX(i)] = v.y;
    }
    __syncthreads();
    fft512_r8<false>(sre[f], sim[f], tw, tl);
    float2* dst = g_mid + (size_t)((c*NA + b)*NH + row)*GW2;
    #pragma unroll
    for (int j = 0; j < 8; j++) {
        int i = tl + 64*j;
        dst[i] = make_float2(sre[f][IDX(i)], sim[f][IDX(i)]);
    }
}

// -------- P2: 4 cols/block: column-FFT with zero-padded rows ----------------
__global__ void __launch_bounds__(256)
p2_colfft() {
    __shared__ float sre[4][SMEM_N], sim[4][SMEM_N];
    __shared__ float2 tw[512];
    int t = threadIdx.x;
    build_tw(tw, t);
    int j0 = blockIdx.x*4, b = blockIdx.y, c = blockIdx.z;
    int f2 = t & 3, tl2 = t >> 2;          // coalesced fill/store mapping
    const float2* src = g_mid + (size_t)((c*NA + b)*NH)*GW2;
    #pragma unroll
    for (int j = 0; j < 8; j++) {
        int i = tl2 + 64*j;
        float2 v = make_float2(0.f, 0.f);
        if (j >= 2 && j < 6)
            v = src[(size_t)(i - 128)*GW2 + j0 + f2];
        sre[f2][IDX(i)] = v.x; sim[f2][IDX(i)] = v.y;
    }
    __syncthreads();
    fft512_r8<false>(sre[t >> 6], sim[t >> 6], tw, t & 63);
    float2* dst = g_full + (size_t)(c*NA + b)*FREQ;
    #pragma unroll
    for (int j = 0; j < 8; j++) {
        int i = tl2 + 64*j;
        dst[(size_t)i*GW2 + j0 + f2] = make_float2(sre[f2][IDX(i)], sim[f2][IDX(i)]);
    }
}

// -------- P3: per-frequency [A,A] contraction, in place, K read once --------
__global__ void __launch_bounds__(256)
p3_contract(const float* __restrict__ kr, const float* __restrict__ ki) {
    int idx = blockIdx.x*256 + threadIdx.x;
    const float SCALE = 1.0f / 65536.0f;     // OS^2 / (512*512) ortho norms
    float2 K[NA*NA];
    #pragma unroll
    for (int q = 0; q < NA*NA; q++) {
        size_t o = (size_t)q*FREQ + idx;
        K[q] = make_float2(kr[o]*SCALE, ki[o]*SCALE);
    }
    for (int c = 0; c < NC; c++) {
        float2 fx[NA];
        #pragma unroll
        for (int b = 0; b < NA; b++)
            fx[b] = g_full[(size_t)(c*NA + b)*FREQ + idx];
        #pragma unroll
        for (int a = 0; a < NA; a++) {
            float2 acc = make_float2(0.f, 0.f);
            #pragma unroll
            for (int b = 0; b < NA; b++) {
                float2 kv = K[a*NA + b];
                float2 f  = fx[b];
                acc.x += f.x*kv.x - f.y*kv.y;
                acc.y += f.x*kv.y + f.y*kv.x;
            }
            g_full[(size_t)(c*NA + a)*FREQ + idx] = acc;
        }
    }
}

// -------- P4: 4 cols/block: column-IFFT, keep only rows 128..383 ------------
__global__ void __launch_bounds__(256)
p4_colifft() {
    __shared__ float sre[4][SMEM_N], sim[4][SMEM_N];
    __shared__ float2 tw[512];
    int t = threadIdx.x;
    build_tw(tw, t);
    int j0 = blockIdx.x*4, a = blockIdx.y, c = blockIdx.z;
    int f2 = t & 3, tl2 = t >> 2;
    const float2* src = g_full + (size_t)(c*NA + a)*FREQ;
    #pragma unroll
    for (int j = 0; j < 8; j++) {
        int i = tl2 + 64*j;
        float2 v = src[(size_t)i*GW2 + j0 + f2];
        sre[f2][IDX(i)] = v.x; sim[f2][IDX(i)] = v.y;
    }
    __syncthreads();
    fft512_r8<true>(sre[t >> 6], sim[t >> 6], tw, t & 63);
    float2* dst = g_mid + (size_t)((c*NA + a)*NH)*GW2;
    #pragma unroll
    for (int j = 2; j < 6; j++) {
        int i = tl2 + 64*j;
        dst[(size_t)(i - 128)*GW2 + j0 + f2] = make_float2(sre[f2][IDX(i)], sim[f2][IDX(i)]);
    }
}

// -------- P5: 4 coils in parallel x3 iters: row-IFFT, crop, conj(mps), sum --
__global__ void __launch_bounds__(256)
p5_combine(const float* __restrict__ mr, const float* __restrict__ mi,
           float* __restrict__ out, int out_cap) {
    __shared__ float sre[4][SMEM_N], sim[4][SMEM_N];
    __shared__ float2 tw[512];
    __shared__ float2 sacc[4][256];
    int t = threadIdx.x;
    build_tw(tw, t);
    int f = t >> 6, tl = t & 63;
    int r = blockIdx.x, a = blockIdx.y;
    float2 acc[4] = {{0,0},{0,0},{0,0},{0,0}};
    for (int it = 0; it < 3; it++) {
        int c = it*4 + f;
        const float2* src = g_mid + (size_t)((c*NA + a)*NH + r)*GW2;
        __syncthreads();               // previous iter's smem reads done
        #pragma unroll
        for (int j = 0; j < 8; j++) {
            int i = tl + 64*j;
            float2 v = src[i];
            sre[f][IDX(i)] = v.x; sim[f][IDX(i)] = v.y;
        }
        __syncthreads();
        fft512_r8<true>(sre[f], sim[f], tw, tl);
        #pragma unroll
        for (int j = 2; j < 6; j++) {
            int i = tl + 64*j;
            int col = i - 128;
            float2 v = make_float2(sre[f][IDX(i)], sim[f][IDX(i)]);
            int mo = (c*NH + r)*NW + col;
            float2 m = make_float2(mr[mo], -mi[mo]);
            acc[j-2] = cadd(acc[j-2], cmul(v, m));
        }
    }
    #pragma unroll
    for (int jj = 0; jj < 4; jj++)
        sacc[f][tl + 64*jj] = acc[jj];
    __syncthreads();
    int col = t;
    float2 s = cadd(cadd(sacc[0][col], sacc[1][col]),
                    cadd(sacc[2][col], sacc[3][col]));
    int i = (a*NH + r)*NW + col;
    if (i        < out_cap) out[i]        = s.x;   // real plane
    if (i + SZ_X < out_cap) out[i + SZ_X] = s.y;   // imag plane
}

extern "C" void kernel_launch(void* const* d_in, const int* in_sizes, int n_in,
                              void* d_out, int out_size) {
    // ---- strict binding by verified size fingerprint (validated in R5) ----
    const float *ptr_by_sz[3][2] = {{0,0},{0,0},{0,0}};
    int idx_by_sz[3][2] = {{-1,-1},{-1,-1},{-1,-1}};
    bool ok = (n_in == 6);
    if (ok) {
        for (int i = 0; i < 6; i++) {
            long long s = in_sizes[i];
            int which = -1;
            if (s == SZ_X   || s == (long long)SZ_X*4)   which = 0;
            else if (s == SZ_MPS || s == (long long)SZ_MPS*4) which = 1;
            else if (s == SZ_K   || s == (long long)SZ_K*4)   which = 2;
            if (which < 0) { ok = false; break; }
            if      (idx_by_sz[which][0] < 0) { idx_by_sz[which][0] = i; ptr_by_sz[which][0] = (const float*)d_in[i]; }
            else if (idx_by_sz[which][1] < 0) { idx_by_sz[which][1] = i; ptr_by_sz[which][1] = (const float*)d_in[i]; }
            else { ok = false; break; }
        }
        if (ok)
            for (int w = 0; w < 3; w++)
                if (idx_by_sz[w][1] < 0) ok = false;
    }
    if (!ok) {
        int n = out_size > 0 ? out_size : 1;
        zero_out<<<(n + 255)/256, 256>>>((float*)d_out, n);
        return;
    }
    bool real_first = (idx_by_sz[0][0] < idx_by_sz[2][0]);
    const float* xr = ptr_by_sz[0][real_first ? 0 : 1];
    const float* xi = ptr_by_sz[0][real_first ? 1 : 0];
    const float* mr = ptr_by_sz[1][real_first ? 0 : 1];
    const float* mi = ptr_by_sz[1][real_first ? 1 : 0];
    const float* kr = ptr_by_sz[2][real_first ? 0 : 1];
    const float* ki = ptr_by_sz[2][real_first ? 1 : 0];

    p1_rowfft <<<dim3(NH/4, NA, NC), 256>>>(xr, xi, mr, mi);
    p2_colfft <<<dim3(GW2/4, NA, NC), 256>>>();
    p3_contract<<<FREQ/256, 256>>>(kr, ki);
    p4_colifft<<<dim3(GW2/4, NA, NC), 256>>>();
    p5_combine<<<dim3(NH, NA), 256>>>(mr, mi, (float*)d_out, out_size);
}

// round 7
// speedup vs baseline: 2.0063x; 1.1641x over previous
#include <cuda_runtime.h>

#define NH 256
#define NW 256
#define GH2 512
#define GW2 512
#define NA 5
#define NC 12
#define FREQ (GH2*GW2)   // 262144

#define SZ_X   (NA*NH*NW)      // 327680
#define SZ_MPS (NC*NH*NW)      // 786432
#define SZ_K   (NA*NA*FREQ)    // 6553600

// Skewed smem index: conflict-free for the radix-8 pass patterns (verified by
// bank enumeration for pass-0/2 reads+writes; pass-1 writes ~1.2x).
#define IDX(i) ((i) + ((i) >> 5) + 8*((i) >> 6))
#define SMEM_N 584             // IDX(511) = 582

// Layouts:
//  g_full: [c][b or a][w(512)][h(512)]  (transposed: h contiguous)
//  g_mid : phase1 = g_midT [c][b][col(512)][row(256)]
//          phase2 = g_mid2 [c][a][row(256)][col(512)]
//  g_KT  : [q=a*5+b][w][h] float2, SCALE prefolded
__device__ float2 g_full[NC*NA*FREQ];      // 125.8 MB
__device__ float2 g_mid [NC*NA*NH*GW2];    // 62.9 MB
__device__ float2 g_KT  [NA*NA*FREQ];      // 52.4 MB

__device__ __forceinline__ float2 cadd(float2 a, float2 b) { return make_float2(a.x+b.x, a.y+b.y); }
__device__ __forceinline__ float2 csub(float2 a, float2 b) { return make_float2(a.x-b.x, a.y-b.y); }
__device__ __forceinline__ float2 cmul(float2 a, float2 b) {
    return make_float2(a.x*b.x - a.y*b.y, a.x*b.y + a.y*b.x);
}

__device__ __forceinline__ void build_tw(float2* tw, int t) {
    #pragma unroll
    for (int u = 0; u < 2; u++) {
        int j = t + 256*u;
        float sv, cv;
        sincosf(-6.283185307179586f * (float)j * (1.0f/512.0f), &sv, &cv);
        tw[j] = make_float2(cv, sv);
    }
}

// In-register DFT-8 (DIF), natural-order outputs.
template<bool INV>
__device__ __forceinline__ void dft8(float2* x) {
    const float H = 0.70710678118654752f;
    float2 t0 = cadd(x[0], x[4]), t4 = csub(x[0], x[4]);
    float2 t1 = cadd(x[1], x[5]), t5 = csub(x[1], x[5]);
    float2 t2 = cadd(x[2], x[6]), t6 = csub(x[2], x[6]);
    float2 t3 = cadd(x[3], x[7]), t7 = csub(x[3], x[7]);
    if (!INV) {
        t5 = make_float2(H*(t5.x + t5.y), H*(t5.y - t5.x));
        t6 = make_float2(t6.y, -t6.x);
        t7 = make_float2(H*(t7.y - t7.x), -H*(t7.x + t7.y));
    } else {
        t5 = make_float2(H*(t5.x - t5.y), H*(t5.x + t5.y));
        t6 = make_float2(-t6.y, t6.x);
        t7 = make_float2(-H*(t7.x + t7.y), H*(t7.x - t7.y));
    }
    float2 u0 = cadd(t0, t2), u2 = csub(t0, t2);
    float2 u1 = cadd(t1, t3), u3 = csub(t1, t3);
    u3 = INV ? make_float2(-u3.y, u3.x) : make_float2(u3.y, -u3.x);
    float2 v0 = cadd(t4, t6), v2 = csub(t4, t6);
    float2 v1 = cadd(t5, t7), v3 = csub(t5, t7);
    v3 = INV ? make_float2(-v3.y, v3.x) : make_float2(v3.y, -v3.x);
    x[0] = cadd(u0, u1); x[4] = csub(u0, u1);
    x[2] = cadd(u2, u3); x[6] = csub(u2, u3);
    x[1] = cadd(v0, v1); x[5] = csub(v0, v1);
    x[3] = cadd(v2, v3); x[7] = csub(v2, v3);
}

// 512-pt radix-8 Stockham with register IO.
// In:  x[j] = point (tl + 64j).  Out: x[r] = frequency (tl + 64r).
// Pass 0 writes smem; caller must sync before call if smem is being reused.
// No sync after the final read: caller must sync before writing smem again.
template<bool INV>
__device__ __forceinline__ void fft512_reg(float2* x, float* re, float* im,
                                           const float2* tw, int tl) {
    // pass 0 (s=1)
    dft8<INV>(x);
    #pragma unroll
    for (int r = 0; r < 8; r++) {
        float2 v = x[r];
        if (r > 0) {
            float2 w = tw[tl*r];
            float wy = INV ? -w.y : w.y;
            v = make_float2(x[r].x*w.x - x[r].y*wy, x[r].x*wy + x[r].y*w.x);
        }
        int o = 8*tl + r;
        re[IDX(o)] = v.x; im[IDX(o)] = v.y;
    }
    __syncthreads();
    // pass 1 (s=8)
    #pragma unroll
    for (int j = 0; j < 8; j++) {
        int i = tl + 64*j;
        x[j] = make_float2(re[IDX(i)], im[IDX(i)]);
    }
    __syncthreads();
    dft8<INV>(x);
    {
        int q = tl & 7, p = tl >> 3;
        int ob = q + 64*p;
        #pragma unroll
        for (int r = 0; r < 8; r++) {
            float2 v = x[r];
            if (r > 0) {
                float2 w = tw[(p*r) << 3];
                float wy = INV ? -w.y : w.y;
                v = make_float2(x[r].x*w.x - x[r].y*wy, x[r].x*wy + x[r].y*w.x);
            }
            int o = ob + 8*r;
            re[IDX(o)] = v.x; im[IDX(o)] = v.y;
        }
    }
    __syncthreads();
    // pass 2 (s=64)
    #pragma unroll
    for (int j = 0; j < 8; j++) {
        int i = tl + 64*j;
        x[j] = make_float2(re[IDX(i)], im[IDX(i)]);
    }
    dft8<INV>(x);
}

__global__ void zero_out(float* __restrict__ o, int n) {
    int i = blockIdx.x*256 + threadIdx.x;
    if (i < n) o[i] = 0.f;
}

// -------- P0: transpose K -> g_KT[q][w][h], SCALE folded --------------------
__global__ void __launch_bounds__(256)
p0_ktrans(const float* __restrict__ kr, const float* __restrict__ ki) {
    __shared__ float tre[32][33], tim[32][33];
    const float SCALE = 1.0f / 65536.0f;     // OS^2 / (512*512) ortho norms
    int q = blockIdx.z;
    int w0 = blockIdx.x*32, h0 = blockIdx.y*32;
    int tx = threadIdx.x & 31, ty = threadIdx.x >> 5;
    size_t base = (size_t)q*FREQ;
    #pragma unroll
    for (int dy = 0; dy < 4; dy++) {
        int h = h0 + ty + 8*dy;
        size_t o = base + (size_t)h*GW2 + w0 + tx;
        tre[ty + 8*dy][tx] = kr[o]*SCALE;
        tim[ty + 8*dy][tx] = ki[o]*SCALE;
    }
    __syncthreads();
    #pragma unroll
    for (int dy = 0; dy < 4; dy++) {
        int w = w0 + ty + 8*dy;
        g_KT[base + (size_t)w*GH2 + h0 + tx] =
            make_float2(tre[tx][ty + 8*dy], tim[tx][ty + 8*dy]);
    }
}

// -------- P1: 4 rows/block: row-FFT of padded x[b]*mps[c], out transposed ---
__global__ void __launch_bounds__(256)
p1_rowfft(const float* __restrict__ xr, const float* __restrict__ xi,
          const float* __restrict__ mr, const float* __restrict__ mi) {
    __shared__ float sre[4][SMEM_N], sim[4][SMEM_N];
    __shared__ float2 tw[512];
    int t = threadIdx.x;
    build_tw(tw, t);
    int f = t >> 6, tl = t & 63;
    int row = blockIdx.x*4 + f;
    int b = blockIdx.y, c = blockIdx.z;
    float2 x[8];
    #pragma unroll
    for (int j = 0; j < 8; j++) {
        int i = tl + 64*j;
        float2 v = make_float2(0.f, 0.f);
        if (j >= 2 && j < 6) {
            int col = i - 128;
            int xo = (b*NH + row)*NW + col;
            int mo = (c*NH + row)*NW + col;
            v = cmul(make_float2(xr[xo], xi[xo]), make_float2(mr[mo], mi[mo]));
        }
        x[j] = v;
    }
    __syncthreads();                       // tw table ready
    fft512_reg<false>(x, sre[f], sim[f], tw, tl);
    // stage: x[r] = col (tl + 64r) -> smem natural, then transpose-write
    __syncthreads();
    #pragma unroll
    for (int r = 0; r < 8; r++) {
        int o = tl + 64*r;
        sre[f][IDX(o)] = x[r].x; sim[f][IDX(o)] = x[r].y;
    }
    __syncthreads();
    int f2 = t & 3, tl2 = t >> 2;
    float2* dst = g_mid + (size_t)(c*NA + b)*GW2*NH;   // [col][row]
    int rowbase = blockIdx.x*4 + f2;
    #pragma unroll
    for (int j = 0; j < 8; j++) {
        int i = tl2 + 64*j;                // col
        dst[(size_t)i*NH + rowbase] = make_float2(sre[f2][IDX(i)], sim[f2][IDX(i)]);
    }
}

// -------- P2: 4 cols/block: col-FFT, direct reg IO (g_midT -> g_full) -------
__global__ void __launch_bounds__(256)
p2_colfft() {
    __shared__ float sre[4][SMEM_N], sim[4][SMEM_N];
    __shared__ float2 tw[512];
    int t = threadIdx.x;
    build_tw(tw, t);
    int f = t >> 6, tl = t & 63;
    int w = blockIdx.x*4 + f, b = blockIdx.y, c = blockIdx.z;
    const float2* src = g_mid + ((size_t)(c*NA + b)*GW2 + w)*NH;  // [col][row]
    float2 x[8];
    #pragma unroll
    for (int j = 0; j < 8; j++) {
        int i = tl + 64*j;
        x[j] = (j >= 2 && j < 6) ? src[i - 128] : make_float2(0.f, 0.f);
    }
    __syncthreads();
    fft512_reg<false>(x, sre[f], sim[f], tw, tl);
    float2* dst = g_full + ((size_t)(c*NA + b)*GW2 + w)*GH2;      // [w][h]
    #pragma unroll
    for (int r = 0; r < 8; r++)
        dst[tl + 64*r] = x[r];
}

// -------- P3: per-frequency [A,A] contraction, in place ---------------------
__global__ void __launch_bounds__(256)
p3_contract() {
    int idx = blockIdx.x*256 + threadIdx.x;
    float2 K[NA*NA];
    #pragma unroll
    for (int q = 0; q < NA*NA; q++)
        K[q] = g_KT[(size_t)q*FREQ + idx];
    for (int c = 0; c < NC; c++) {
        float2 fx[NA];
        #pragma unroll
        for (int b = 0; b < NA; b++)
            fx[b] = g_full[(size_t)(c*NA + b)*FREQ + idx];
        #pragma unroll
        for (int a = 0; a < NA; a++) {
            float2 acc = make_float2(0.f, 0.f);
            #pragma unroll
            for (int b = 0; b < NA; b++) {
                float2 kv = K[a*NA + b];
                float2 f  = fx[b];
                acc.x += f.x*kv.x - f.y*kv.y;
                acc.y += f.x*kv.y + f.y*kv.x;
            }
            g_full[(size_t)(c*NA + a)*FREQ + idx] = acc;
        }
    }
}

// -------- P4: 4 w/block: col-IFFT (over h), crop rows, out [row][col] -------
__global__ void __launch_bounds__(256)
p4_colifft() {
    __shared__ float sre[4][SMEM_N], sim[4][SMEM_N];
    __shared__ float2 tw[512];
    int t = threadIdx.x;
    build_tw(tw, t);
    int f = t >> 6, tl = t & 63;
    int w = blockIdx.x*4 + f, a = blockIdx.y, c = blockIdx.z;
    const float2* src = g_full + ((size_t)(c*NA + a)*GW2 + w)*GH2;  // [w][h]
    float2 x[8];
    #pragma unroll
    for (int j = 0; j < 8; j++)
        x[j] = src[tl + 64*j];
    __syncthreads();
    fft512_reg<true>(x, sre[f], sim[f], tw, tl);
    // stage rows 128..383 (r=2..5) -> transpose-write to [row][col]
    __syncthreads();
    #pragma unroll
    for (int r = 2; r < 6; r++) {
        int o = tl + 64*r;
        sre[f][IDX(o)] = x[r].x; sim[f][IDX(o)] = x[r].y;
    }
    __syncthreads();
    int f2 = t & 3, tl2 = t >> 2;
    float2* dst = g_mid + (size_t)(c*NA + a)*NH*GW2;   // [row][col]
    int wb = blockIdx.x*4 + f2;
    #pragma unroll
    for (int j = 2; j < 6; j++) {
        int i = tl2 + 64*j;                // h
        dst[(size_t)(i - 128)*GW2 + wb] = make_float2(sre[f2][IDX(i)], sim[f2][IDX(i)]);
    }
}

// -------- P5: 4 coils x3 iters: row-IFFT, crop, conj(mps), sum_c ------------
__global__ void __launch_bounds__(256)
p5_combine(const float* __restrict__ mr, const float* __restrict__ mi,
           float* __restrict__ out, int out_cap) {
    __shared__ float sre[4][SMEM_N], sim[4][SMEM_N];
    __shared__ float2 tw[512];
    __shared__ float2 sacc[4][256];
    int t = threadIdx.x;
    build_tw(tw, t);
    int f = t >> 6, tl = t & 63;
    int r = blockIdx.x, a = blockIdx.y;
    float2 acc[4] = {{0,0},{0,0},{0,0},{0,0}};
    for (int it = 0; it < 3; it++) {
        int c = it*4 + f;
        const float2* src = g_mid + ((size_t)(c*NA + a)*NH + r)*GW2;  // [row][col]
        float2 x[8];
        #pragma unroll
        for (int j = 0; j < 8; j++)
            x[j] = src[tl + 64*j];
        __syncthreads();               // smem (tw at it=0; prior pass reads after)
        fft512_reg<true>(x, sre[f], sim[f], tw, tl);
        #pragma unroll
        for (int rr = 2; rr < 6; rr++) {
            int col = tl + 64*rr - 128;
            int mo = (c*NH + r)*NW + col;
            float2 m = make_float2(mr[mo], -mi[mo]);
            acc[rr-2] = cadd(acc[rr-2], cmul(x[rr], m));
        }
    }
    #pragma unroll
    for (int jj = 0; jj < 4; jj++)
        sacc[f][tl + 64*jj] = acc[jj];
    __syncthreads();
    int col = t;
    float2 s = cadd(cadd(sacc[0][col], sacc[1][col]),
                    cadd(sacc[2][col], sacc[3][col]));
    int i = (a*NH + r)*NW + col;
    if (i        < out_cap) out[i]        = s.x;   // real plane
    if (i + SZ_X < out_cap) out[i + SZ_X] = s.y;   // imag plane
}

extern "C" void kernel_launch(void* const* d_in, const int* in_sizes, int n_in,
                              void* d_out, int out_size) {
    // ---- strict binding by verified size fingerprint (validated in R5) ----
    const float *ptr_by_sz[3][2] = {{0,0},{0,0},{0,0}};
    int idx_by_sz[3][2] = {{-1,-1},{-1,-1},{-1,-1}};
    bool ok = (n_in == 6);
    if (ok) {
        for (int i = 0; i < 6; i++) {
            long long s = in_sizes[i];
            int which = -1;
            if (s == SZ_X   || s == (long long)SZ_X*4)   which = 0;
            else if (s == SZ_MPS || s == (long long)SZ_MPS*4) which = 1;
            else if (s == SZ_K   || s == (long long)SZ_K*4)   which = 2;
            if (which < 0) { ok = false; break; }
            if      (idx_by_sz[which][0] < 0) { idx_by_sz[which][0] = i; ptr_by_sz[which][0] = (const float*)d_in[i]; }
            else if (idx_by_sz[which][1] < 0) { idx_by_sz[which][1] = i; ptr_by_sz[which][1] = (const float*)d_in[i]; }
            else { ok = false; break; }
        }
        if (ok)
            for (int w = 0; w < 3; w++)
                if (idx_by_sz[w][1] < 0) ok = false;
    }
    if (!ok) {
        int n = out_size > 0 ? out_size : 1;
        zero_out<<<(n + 255)/256, 256>>>((float*)d_out, n);
        return;
    }
    bool real_first = (idx_by_sz[0][0] < idx_by_sz[2][0]);
    const float* xr = ptr_by_sz[0][real_first ? 0 : 1];
    const float* xi = ptr_by_sz[0][real_first ? 1 : 0];
    const float* mr = ptr_by_sz[1][real_first ? 0 : 1];
    const float* mi = ptr_by_sz[1][real_first ? 1 : 0];
    const float* kr = ptr_by_sz[2][real_first ? 0 : 1];
    const float* ki = ptr_by_sz[2][real_first ? 1 : 0];

    p0_ktrans <<<dim3(16, 16, NA*NA), 256>>>(kr, ki);
    p1_rowfft <<<dim3(NH/4, NA, NC), 256>>>(xr, xi, mr, mi);
    p2_colfft <<<dim3(GW2/4, NA, NC), 256>>>();
    p3_contract<<<FREQ/256, 256>>>();
    p4_colifft<<<dim3(GW2/4, NA, NC), 256>>>();
    p5_combine<<<dim3(NH, NA), 256>>>(mr, mi, (float*)d_out, out_size);
}